// round 7
// baseline (speedup 1.0000x reference)
#include <cuda_runtime.h>
#include <math.h>
#include <stdint.h>

#define NLEV 16
#define THASH (1u << 19)
#define EBLK 256           // encode block
#define MBLK 128           // mlp block (each thread handles 2 points)
#define NMAX (1 << 20)
#define ACT_STRIDE 68      // 17 float4 -> conflict-free LDS.128
#define WTOT 10436         // 2048 + 4096 + 4096 + 192 + 4
#define NCHUNK 8

struct Res4 { int v[NLEV][4]; };

// Feature scratch, level-major for coalesced writes (A) and reads (B).
__device__ float2 g_feat[NLEV][NMAX];

// ---- packed f32x2 helpers -------------------------------------------------
__device__ __forceinline__ void fma2(unsigned long long& d,
                                     unsigned long long a,
                                     unsigned long long b) {
    asm("fma.rn.f32x2 %0, %1, %2, %0;" : "+l"(d) : "l"(a), "l"(b));
}
__device__ __forceinline__ float2 upk(unsigned long long v) {
    float2 r; asm("mov.b64 {%0,%1}, %2;" : "=f"(r.x), "=f"(r.y) : "l"(v)); return r;
}

// ---------------------------------------------------------------------------
// Kernel A: multi-res 4D hash encode over [base, base+cnt). L2-sector bound.
// ---------------------------------------------------------------------------
__global__ void __launch_bounds__(EBLK, 4)
ingp_encode(const float4* __restrict__ x,
            const float2* __restrict__ table,
            int base, int cnt, Res4 res)
{
    const int i = blockIdx.x * EBLK + threadIdx.x;
    if (i >= cnt) return;
    const int n = base + i;
    const float4 xv = __ldg(x + n);

    #pragma unroll 1
    for (int l = 0; l < NLEV; l++) {
        const float r0 = (float)res.v[l][0] - 1.0f;
        const float r1 = (float)res.v[l][1] - 1.0f;
        const float r2 = (float)res.v[l][2] - 1.0f;
        const float r3 = (float)res.v[l][3] - 1.0f;
        float p0 = xv.x * r0, p1 = xv.y * r1, p2 = xv.z * r2, p3 = xv.w * r3;
        float b0 = floorf(p0), b1 = floorf(p1), b2 = floorf(p2), b3 = floorf(p3);
        float f0 = p0 - b0, f1 = p1 - b1, f2 = p2 - b2, f3 = p3 - b3;
        float g0 = 1.f - f0, g1 = 1.f - f1, g2 = 1.f - f2, g3 = 1.f - f3;

        unsigned ha0 = (unsigned)(int)b0;                 unsigned hb0 = ha0 + 1u;
        unsigned ha1 = (unsigned)(int)b1 * 2654435761u;   unsigned hb1 = ha1 + 2654435761u;
        unsigned ha2 = (unsigned)(int)b2 * 805459861u;    unsigned hb2 = ha2 + 805459861u;
        unsigned ha3 = (unsigned)(int)b3 * 3674653429u;   unsigned hb3 = ha3 + 3674653429u;

        unsigned hxy[4] = { ha0 ^ ha1, hb0 ^ ha1, ha0 ^ hb1, hb0 ^ hb1 };
        unsigned hzw[4] = { ha2 ^ ha3, hb2 ^ ha3, ha2 ^ hb3, hb2 ^ hb3 };
        float    wxy[4] = { g0 * g1,  f0 * g1,  g0 * f1,  f0 * f1 };
        float    wzw[4] = { g2 * g3,  f2 * g3,  g2 * f3,  f2 * f3 };

        const float2* tl = table + ((size_t)l << 19);
        float acc0 = 0.f, acc1 = 0.f;
        #pragma unroll
        for (int c = 0; c < 16; c++) {
            unsigned idx = (hxy[c & 3] ^ hzw[(c >> 2) & 3]) & (THASH - 1u);
            float2 t2 = __ldg(tl + idx);
            float w = wxy[c & 3] * wzw[(c >> 2) & 3];
            acc0 = fmaf(w, t2.x, acc0);
            acc1 = fmaf(w, t2.y, acc1);
        }
        g_feat[l][n] = make_float2(acc0, acc1);
    }
}

// ---------------------------------------------------------------------------
// Kernel B: MLP (R5 form: 2 points/thread, FFMA2, smem weight broadcast),
// over points [base, base+cnt).
// ---------------------------------------------------------------------------
__global__ void __launch_bounds__(MBLK, 2)
ingp_mlp(const float* __restrict__ w0,
         const float* __restrict__ w1,
         const float* __restrict__ w2,
         const float* __restrict__ w_out,
         const float* __restrict__ b_out,
         float* __restrict__ out, int base, int N)
{
    extern __shared__ float sm[];
    float* s_w0 = sm;                       // [64][32]
    float* s_w1 = sm + 2048;                // [64][64]
    float* s_w2 = sm + 6144;                // [64][64]
    float* s_wo = sm + 10240;               // [3][64]
    float* s_bo = sm + 10432;               // 3 (+pad)
    float* s_actA = sm + WTOT;              // MBLK * ACT_STRIDE
    float* s_actB = s_actA + MBLK * ACT_STRIDE;

    const int tid = threadIdx.x;

    {   // cooperative weight load
        float4* dw0 = (float4*)s_w0; const float4* sw0 = (const float4*)w0;
        float4* dw1 = (float4*)s_w1; const float4* sw1 = (const float4*)w1;
        float4* dw2 = (float4*)s_w2; const float4* sw2 = (const float4*)w2;
        float4* dwo = (float4*)s_wo; const float4* swo = (const float4*)w_out;
        #pragma unroll 1
        for (int i = tid; i < 512;  i += MBLK) dw0[i] = sw0[i];
        #pragma unroll 1
        for (int i = tid; i < 1024; i += MBLK) dw1[i] = sw1[i];
        #pragma unroll 1
        for (int i = tid; i < 1024; i += MBLK) dw2[i] = sw2[i];
        if (tid < 48) dwo[tid] = swo[tid];
        if (tid < 3)  s_bo[tid] = b_out[tid];
    }
    __syncthreads();

    const int nA = base + blockIdx.x * (2 * MBLK) + tid;
    const int nB = nA + MBLK;
    if (nA >= N) return;
    const bool hasB = (nB < N);

    float* arowA = s_actA + tid * ACT_STRIDE;
    float* arowB = s_actB + tid * ACT_STRIDE;

    unsigned long long finA[32], finB[32];

    #pragma unroll
    for (int l = 0; l < NLEV; l++) {
        finA[l] = __ldg((const unsigned long long*)&g_feat[l][nA]);
        finB[l] = hasB ? __ldg((const unsigned long long*)&g_feat[l][nB]) : 0ull;
    }

    // ---- layer 0: 32 -> 64, ReLU ----
    #pragma unroll 1
    for (int j = 0; j < 64; j += 4) {
        unsigned long long a0 = 0, a1 = 0, a2 = 0, a3 = 0;
        unsigned long long c0 = 0, c1 = 0, c2 = 0, c3 = 0;
        const ulonglong2* r0 = (const ulonglong2*)(s_w0 + (j + 0) * 32);
        const ulonglong2* r1 = (const ulonglong2*)(s_w0 + (j + 1) * 32);
        const ulonglong2* r2 = (const ulonglong2*)(s_w0 + (j + 2) * 32);
        const ulonglong2* r3 = (const ulonglong2*)(s_w0 + (j + 3) * 32);
        #pragma unroll
        for (int q = 0; q < 8; q++) {
            unsigned long long pA0 = finA[2*q], pA1 = finA[2*q+1];
            unsigned long long pB0 = finB[2*q], pB1 = finB[2*q+1];
            ulonglong2 wa = r0[q];
            fma2(a0, pA0, wa.x); fma2(a0, pA1, wa.y);
            fma2(c0, pB0, wa.x); fma2(c0, pB1, wa.y);
            ulonglong2 wb = r1[q];
            fma2(a1, pA0, wb.x); fma2(a1, pA1, wb.y);
            fma2(c1, pB0, wb.x); fma2(c1, pB1, wb.y);
            ulonglong2 wc = r2[q];
            fma2(a2, pA0, wc.x); fma2(a2, pA1, wc.y);
            fma2(c2, pB0, wc.x); fma2(c2, pB1, wc.y);
            ulonglong2 wd = r3[q];
            fma2(a3, pA0, wd.x); fma2(a3, pA1, wd.y);
            fma2(c3, pB0, wd.x); fma2(c3, pB1, wd.y);
        }
        float2 s0 = upk(a0), s1 = upk(a1), s2 = upk(a2), s3 = upk(a3);
        float2 t0 = upk(c0), t1 = upk(c1), t2 = upk(c2), t3 = upk(c3);
        ((float4*)arowA)[j >> 2] = make_float4(fmaxf(s0.x + s0.y, 0.f),
                                               fmaxf(s1.x + s1.y, 0.f),
                                               fmaxf(s2.x + s2.y, 0.f),
                                               fmaxf(s3.x + s3.y, 0.f));
        ((float4*)arowB)[j >> 2] = make_float4(fmaxf(t0.x + t0.y, 0.f),
                                               fmaxf(t1.x + t1.y, 0.f),
                                               fmaxf(t2.x + t2.y, 0.f),
                                               fmaxf(t3.x + t3.y, 0.f));
    }

    // ---- layers 1 & 2: 64 -> 64, ReLU ----
    #pragma unroll 1
    for (int layer = 0; layer < 2; layer++) {
        const float* s_w = (layer == 0) ? s_w1 : s_w2;
        #pragma unroll
        for (int q = 0; q < 16; q++) {
            ulonglong2 vA = ((const ulonglong2*)arowA)[q];
            ulonglong2 vB = ((const ulonglong2*)arowB)[q];
            finA[2*q] = vA.x; finA[2*q+1] = vA.y;
            finB[2*q] = vB.x; finB[2*q+1] = vB.y;
        }
        #pragma unroll 1
        for (int j = 0; j < 64; j += 4) {
            unsigned long long a0 = 0, a1 = 0, a2 = 0, a3 = 0;
            unsigned long long c0 = 0, c1 = 0, c2 = 0, c3 = 0;
            const ulonglong2* r0 = (const ulonglong2*)(s_w + (j + 0) * 64);
            const ulonglong2* r1 = (const ulonglong2*)(s_w + (j + 1) * 64);
            const ulonglong2* r2 = (const ulonglong2*)(s_w + (j + 2) * 64);
            const ulonglong2* r3 = (const ulonglong2*)(s_w + (j + 3) * 64);
            #pragma unroll
            for (int q = 0; q < 16; q++) {
                unsigned long long pA0 = finA[2*q], pA1 = finA[2*q+1];
                unsigned long long pB0 = finB[2*q], pB1 = finB[2*q+1];
                ulonglong2 wa = r0[q];
                fma2(a0, pA0, wa.x); fma2(a0, pA1, wa.y);
                fma2(c0, pB0, wa.x); fma2(c0, pB1, wa.y);
                ulonglong2 wb = r1[q];
                fma2(a1, pA0, wb.x); fma2(a1, pA1, wb.y);
                fma2(c1, pB0, wb.x); fma2(c1, pB1, wb.y);
                ulonglong2 wc = r2[q];
                fma2(a2, pA0, wc.x); fma2(a2, pA1, wc.y);
                fma2(c2, pB0, wc.x); fma2(c2, pB1, wc.y);
                ulonglong2 wd = r3[q];
                fma2(a3, pA0, wd.x); fma2(a3, pA1, wd.y);
                fma2(c3, pB0, wd.x); fma2(c3, pB1, wd.y);
            }
            float2 s0 = upk(a0), s1 = upk(a1), s2 = upk(a2), s3 = upk(a3);
            float2 t0 = upk(c0), t1 = upk(c1), t2 = upk(c2), t3 = upk(c3);
            ((float4*)arowA)[j >> 2] = make_float4(fmaxf(s0.x + s0.y, 0.f),
                                                   fmaxf(s1.x + s1.y, 0.f),
                                                   fmaxf(s2.x + s2.y, 0.f),
                                                   fmaxf(s3.x + s3.y, 0.f));
            ((float4*)arowB)[j >> 2] = make_float4(fmaxf(t0.x + t0.y, 0.f),
                                                   fmaxf(t1.x + t1.y, 0.f),
                                                   fmaxf(t2.x + t2.y, 0.f),
                                                   fmaxf(t3.x + t3.y, 0.f));
        }
    }

    // ---- output layer: 64 -> 3, + bias ----
    #pragma unroll
    for (int q = 0; q < 16; q++) {
        ulonglong2 vA = ((const ulonglong2*)arowA)[q];
        ulonglong2 vB = ((const ulonglong2*)arowB)[q];
        finA[2*q] = vA.x; finA[2*q+1] = vA.y;
        finB[2*q] = vB.x; finB[2*q+1] = vB.y;
    }
    {
        unsigned long long a0 = 0, a1 = 0, a2 = 0;
        unsigned long long c0 = 0, c1 = 0, c2 = 0;
        const ulonglong2* r0 = (const ulonglong2*)(s_wo + 0);
        const ulonglong2* r1 = (const ulonglong2*)(s_wo + 64);
        const ulonglong2* r2 = (const ulonglong2*)(s_wo + 128);
        #pragma unroll
        for (int q = 0; q < 16; q++) {
            unsigned long long pA0 = finA[2*q], pA1 = finA[2*q+1];
            unsigned long long pB0 = finB[2*q], pB1 = finB[2*q+1];
            ulonglong2 wa = r0[q];
            fma2(a0, pA0, wa.x); fma2(a0, pA1, wa.y);
            fma2(c0, pB0, wa.x); fma2(c0, pB1, wa.y);
            ulonglong2 wb = r1[q];
            fma2(a1, pA0, wb.x); fma2(a1, pA1, wb.y);
            fma2(c1, pB0, wb.x); fma2(c1, pB1, wb.y);
            ulonglong2 wc = r2[q];
            fma2(a2, pA0, wc.x); fma2(a2, pA1, wc.y);
            fma2(c2, pB0, wc.x); fma2(c2, pB1, wc.y);
        }
        float2 s0 = upk(a0), s1 = upk(a1), s2 = upk(a2);
        float2 t0 = upk(c0), t1 = upk(c1), t2 = upk(c2);
        const float bo0 = s_bo[0], bo1 = s_bo[1], bo2 = s_bo[2];
        size_t obA = (size_t)nA * 3;
        out[obA + 0] = bo0 + s0.x + s0.y;
        out[obA + 1] = bo1 + s1.x + s1.y;
        out[obA + 2] = bo2 + s2.x + s2.y;
        if (hasB) {
            size_t obB = (size_t)nB * 3;
            out[obB + 0] = bo0 + t0.x + t0.y;
            out[obB + 1] = bo1 + t1.x + t1.y;
            out[obB + 2] = bo2 + t2.x + t2.y;
        }
    }
}

extern "C" void kernel_launch(void* const* d_in, const int* in_sizes, int n_in,
                              void* d_out, int out_size)
{
    const float4* x     = (const float4*)d_in[0];
    const float2* table = (const float2*)d_in[1];
    const float*  w0    = (const float*)d_in[2];
    const float*  w1    = (const float*)d_in[3];
    const float*  w2    = (const float*)d_in[4];
    const float*  w_out = (const float*)d_in[5];
    const float*  b_out = (const float*)d_in[6];
    float* out = (float*)d_out;
    const int N = in_sizes[0] / 4;

    // One-time host resources (streams/events are host objects, not device
    // memory; the device work issued per call is identical every call).
    static cudaStream_t side = nullptr;
    static cudaEvent_t evFork = nullptr;
    static cudaEvent_t evE[NCHUNK];
    if (side == nullptr) {
        cudaStreamCreateWithFlags(&side, cudaStreamNonBlocking);
        cudaEventCreateWithFlags(&evFork, cudaEventDisableTiming);
        for (int c = 0; c < NCHUNK; c++)
            cudaEventCreateWithFlags(&evE[c], cudaEventDisableTiming);
    }

    // Replicate numpy's RES computation bit-exactly (same aarch64 glibc pow/floor).
    Res4 res;
    const double minr[4] = {16.0, 16.0, 16.0, 16.0};
    const double maxr[4] = {256.0, 256.0, 256.0, 128.0};
    for (int d = 0; d < 4; d++) {
        double g = pow(maxr[d] / minr[d], 1.0 / 15.0);
        for (int l = 0; l < NLEV; l++) {
            res.v[l][d] = (int)floor(minr[d] * pow(g, (double)l));
        }
    }

    size_t smem = (size_t)(WTOT + 2 * MBLK * ACT_STRIDE) * sizeof(float);
    cudaFuncSetAttribute(ingp_mlp, cudaFuncAttributeMaxDynamicSharedMemorySize, (int)smem);

    // Chunk size: multiple of 256 (MLP CTA coverage) covering N in NCHUNK pieces.
    int chunkPts = ((N + NCHUNK - 1) / NCHUNK + 255) & ~255;

    // Fork: side stream begins after nothing on main (pure fork point).
    cudaEventRecord(evFork, 0);
    cudaStreamWaitEvent(side, evFork, 0);

    // Side stream: all encode chunks back-to-back, event after each.
    for (int c = 0; c < NCHUNK; c++) {
        int base = c * chunkPts;
        int cnt = N - base; if (cnt > chunkPts) cnt = chunkPts;
        if (cnt > 0) {
            int eg = (cnt + EBLK - 1) / EBLK;
            ingp_encode<<<eg, EBLK, 0, side>>>(x, table, base, cnt, res);
        }
        cudaEventRecord(evE[c], side);
    }

    // Main (capture) stream: MLP chunk c after its encode chunk completes.
    for (int c = 0; c < NCHUNK; c++) {
        int base = c * chunkPts;
        int cnt = N - base; if (cnt > chunkPts) cnt = chunkPts;
        cudaStreamWaitEvent(0, evE[c], 0);
        if (cnt > 0) {
            int mg = (cnt + 2 * MBLK - 1) / (2 * MBLK);
            ingp_mlp<<<mg, MBLK, smem>>>(w0, w1, w2, w_out, b_out, out, base, N);
        }
    }
}

// round 8
// speedup vs baseline: 1.6990x; 1.6990x over previous
#include <cuda_runtime.h>
#include <math.h>
#include <stdint.h>

#define NLEV 16
#define THASH (1u << 19)
#define EBLK 256           // encode block
#define MBLK 128           // mlp block (each thread handles 2 points)
#define NMAX (1 << 20)
#define ACT_STRIDE 68      // 17 float4 -> conflict-free LDS.128
#define WTOT 10436         // 2048 + 4096 + 4096 + 192 + 4
#define NBINS 65536        // 16^4 spatial buckets
#define SBLK 256

struct Res4 { int v[NLEV][4]; };

// Feature scratch (sorted order), level-major.
__device__ float2 g_feat[NLEV][NMAX];
// Sort scratch.
__device__ int g_hist[NBINS];
__device__ int g_cursor[NBINS];
__device__ int g_perm[NMAX];

// ---- packed f32x2 helpers -------------------------------------------------
__device__ __forceinline__ void fma2(unsigned long long& d,
                                     unsigned long long a,
                                     unsigned long long b) {
    asm("fma.rn.f32x2 %0, %1, %2, %0;" : "+l"(d) : "l"(a), "l"(b));
}
__device__ __forceinline__ float2 upk(unsigned long long v) {
    float2 r; asm("mov.b64 {%0,%1}, %2;" : "=f"(r.x), "=f"(r.y) : "l"(v)); return r;
}

__device__ __forceinline__ int bucket_key(float4 xv) {
    int k0 = min((int)(xv.x * 16.0f), 15);
    int k1 = min((int)(xv.y * 16.0f), 15);
    int k2 = min((int)(xv.z * 16.0f), 15);
    int k3 = min((int)(xv.w * 16.0f), 15);
    return (((k0 * 16 + k1) * 16 + k2) * 16) + k3;
}

// ---------------------------------------------------------------------------
// Sort kernels: zero hist -> histogram -> exclusive scan -> scatter perm
// ---------------------------------------------------------------------------
__global__ void sort_zero() {
    int i = blockIdx.x * SBLK + threadIdx.x;
    if (i < NBINS) g_hist[i] = 0;
}

__global__ void sort_hist(const float4* __restrict__ x, int N) {
    int n = blockIdx.x * SBLK + threadIdx.x;
    if (n >= N) return;
    atomicAdd(&g_hist[bucket_key(__ldg(x + n))], 1);
}

__global__ void __launch_bounds__(1024, 1) sort_scan() {
    __shared__ int buf[1024];
    __shared__ int carry;
    const int tid = threadIdx.x;
    if (tid == 0) carry = 0;
    __syncthreads();
    #pragma unroll 1
    for (int base = 0; base < NBINS; base += 1024) {
        int v = g_hist[base + tid];
        buf[tid] = v;
        __syncthreads();
        #pragma unroll
        for (int off = 1; off < 1024; off <<= 1) {
            int t = (tid >= off) ? buf[tid - off] : 0;
            __syncthreads();
            buf[tid] += t;
            __syncthreads();
        }
        g_cursor[base + tid] = carry + buf[tid] - v;   // exclusive
        __syncthreads();
        if (tid == 1023) carry += buf[1023];
        __syncthreads();
    }
}

__global__ void sort_scatter(const float4* __restrict__ x, int N) {
    int n = blockIdx.x * SBLK + threadIdx.x;
    if (n >= N) return;
    int pos = atomicAdd(&g_cursor[bucket_key(__ldg(x + n))], 1);
    g_perm[pos] = n;
}

// ---------------------------------------------------------------------------
// Kernel A: multi-res 4D hash encode in SORTED order. Warp lanes are
// spatially adjacent -> corner gathers merge into few L1tex wavefronts.
// ---------------------------------------------------------------------------
__global__ void __launch_bounds__(EBLK, 4)
ingp_encode(const float4* __restrict__ x,
            const float2* __restrict__ table,
            int N, Res4 res)
{
    const int i = blockIdx.x * EBLK + threadIdx.x;
    if (i >= N) return;
    const int n = __ldg(&g_perm[i]);
    const float4 xv = __ldg(x + n);

    #pragma unroll 1
    for (int l = 0; l < NLEV; l++) {
        const float r0 = (float)res.v[l][0] - 1.0f;
        const float r1 = (float)res.v[l][1] - 1.0f;
        const float r2 = (float)res.v[l][2] - 1.0f;
        const float r3 = (float)res.v[l][3] - 1.0f;
        float p0 = xv.x * r0, p1 = xv.y * r1, p2 = xv.z * r2, p3 = xv.w * r3;
        float b0 = floorf(p0), b1 = floorf(p1), b2 = floorf(p2), b3 = floorf(p3);
        float f0 = p0 - b0, f1 = p1 - b1, f2 = p2 - b2, f3 = p3 - b3;
        float g0 = 1.f - f0, g1 = 1.f - f1, g2 = 1.f - f2, g3 = 1.f - f3;

        unsigned ha0 = (unsigned)(int)b0;                 unsigned hb0 = ha0 + 1u;
        unsigned ha1 = (unsigned)(int)b1 * 2654435761u;   unsigned hb1 = ha1 + 2654435761u;
        unsigned ha2 = (unsigned)(int)b2 * 805459861u;    unsigned hb2 = ha2 + 805459861u;
        unsigned ha3 = (unsigned)(int)b3 * 3674653429u;   unsigned hb3 = ha3 + 3674653429u;

        unsigned hxy[4] = { ha0 ^ ha1, hb0 ^ ha1, ha0 ^ hb1, hb0 ^ hb1 };
        unsigned hzw[4] = { ha2 ^ ha3, hb2 ^ ha3, ha2 ^ hb3, hb2 ^ hb3 };
        float    wxy[4] = { g0 * g1,  f0 * g1,  g0 * f1,  f0 * f1 };
        float    wzw[4] = { g2 * g3,  f2 * g3,  g2 * f3,  f2 * f3 };

        const float2* tl = table + ((size_t)l << 19);
        float acc0 = 0.f, acc1 = 0.f;
        #pragma unroll
        for (int c = 0; c < 16; c++) {
            unsigned idx = (hxy[c & 3] ^ hzw[(c >> 2) & 3]) & (THASH - 1u);
            float2 t2 = __ldg(tl + idx);
            float w = wxy[c & 3] * wzw[(c >> 2) & 3];
            acc0 = fmaf(w, t2.x, acc0);
            acc1 = fmaf(w, t2.y, acc1);
        }
        g_feat[l][i] = make_float2(acc0, acc1);
    }
}

// ---------------------------------------------------------------------------
// Kernel B: MLP (R5 proven form: 2 points/thread, FFMA2, smem weight
// broadcast). Reads features in sorted order, scatters outputs via perm.
// ---------------------------------------------------------------------------
__global__ void __launch_bounds__(MBLK, 2)
ingp_mlp(const float* __restrict__ w0,
         const float* __restrict__ w1,
         const float* __restrict__ w2,
         const float* __restrict__ w_out,
         const float* __restrict__ b_out,
         float* __restrict__ out, int N)
{
    extern __shared__ float sm[];
    float* s_w0 = sm;                       // [64][32]
    float* s_w1 = sm + 2048;                // [64][64]
    float* s_w2 = sm + 6144;                // [64][64]
    float* s_wo = sm + 10240;               // [3][64]
    float* s_bo = sm + 10432;               // 3 (+pad)
    float* s_actA = sm + WTOT;              // MBLK * ACT_STRIDE
    float* s_actB = s_actA + MBLK * ACT_STRIDE;

    const int tid = threadIdx.x;

    {   // cooperative weight load
        float4* dw0 = (float4*)s_w0; const float4* sw0 = (const float4*)w0;
        float4* dw1 = (float4*)s_w1; const float4* sw1 = (const float4*)w1;
        float4* dw2 = (float4*)s_w2; const float4* sw2 = (const float4*)w2;
        float4* dwo = (float4*)s_wo; const float4* swo = (const float4*)w_out;
        #pragma unroll 1
        for (int i = tid; i < 512;  i += MBLK) dw0[i] = sw0[i];
        #pragma unroll 1
        for (int i = tid; i < 1024; i += MBLK) dw1[i] = sw1[i];
        #pragma unroll 1
        for (int i = tid; i < 1024; i += MBLK) dw2[i] = sw2[i];
        if (tid < 48) dwo[tid] = swo[tid];
        if (tid < 3)  s_bo[tid] = b_out[tid];
    }
    __syncthreads();

    const int iA = blockIdx.x * (2 * MBLK) + tid;
    const int iB = iA + MBLK;
    if (iA >= N) return;
    const bool hasB = (iB < N);

    float* arowA = s_actA + tid * ACT_STRIDE;
    float* arowB = s_actB + tid * ACT_STRIDE;

    unsigned long long finA[32], finB[32];

    #pragma unroll
    for (int l = 0; l < NLEV; l++) {
        finA[l] = __ldg((const unsigned long long*)&g_feat[l][iA]);
        finB[l] = hasB ? __ldg((const unsigned long long*)&g_feat[l][iB]) : 0ull;
    }

    // ---- layer 0: 32 -> 64, ReLU ----
    #pragma unroll 1
    for (int j = 0; j < 64; j += 4) {
        unsigned long long a0 = 0, a1 = 0, a2 = 0, a3 = 0;
        unsigned long long c0 = 0, c1 = 0, c2 = 0, c3 = 0;
        const ulonglong2* r0 = (const ulonglong2*)(s_w0 + (j + 0) * 32);
        const ulonglong2* r1 = (const ulonglong2*)(s_w0 + (j + 1) * 32);
        const ulonglong2* r2 = (const ulonglong2*)(s_w0 + (j + 2) * 32);
        const ulonglong2* r3 = (const ulonglong2*)(s_w0 + (j + 3) * 32);
        #pragma unroll
        for (int q = 0; q < 8; q++) {
            unsigned long long pA0 = finA[2*q], pA1 = finA[2*q+1];
            unsigned long long pB0 = finB[2*q], pB1 = finB[2*q+1];
            ulonglong2 wa = r0[q];
            fma2(a0, pA0, wa.x); fma2(a0, pA1, wa.y);
            fma2(c0, pB0, wa.x); fma2(c0, pB1, wa.y);
            ulonglong2 wb = r1[q];
            fma2(a1, pA0, wb.x); fma2(a1, pA1, wb.y);
            fma2(c1, pB0, wb.x); fma2(c1, pB1, wb.y);
            ulonglong2 wc = r2[q];
            fma2(a2, pA0, wc.x); fma2(a2, pA1, wc.y);
            fma2(c2, pB0, wc.x); fma2(c2, pB1, wc.y);
            ulonglong2 wd = r3[q];
            fma2(a3, pA0, wd.x); fma2(a3, pA1, wd.y);
            fma2(c3, pB0, wd.x); fma2(c3, pB1, wd.y);
        }
        float2 s0 = upk(a0), s1 = upk(a1), s2 = upk(a2), s3 = upk(a3);
        float2 t0 = upk(c0), t1 = upk(c1), t2 = upk(c2), t3 = upk(c3);
        ((float4*)arowA)[j >> 2] = make_float4(fmaxf(s0.x + s0.y, 0.f),
                                               fmaxf(s1.x + s1.y, 0.f),
                                               fmaxf(s2.x + s2.y, 0.f),
                                               fmaxf(s3.x + s3.y, 0.f));
        ((float4*)arowB)[j >> 2] = make_float4(fmaxf(t0.x + t0.y, 0.f),
                                               fmaxf(t1.x + t1.y, 0.f),
                                               fmaxf(t2.x + t2.y, 0.f),
                                               fmaxf(t3.x + t3.y, 0.f));
    }

    // ---- layers 1 & 2: 64 -> 64, ReLU ----
    #pragma unroll 1
    for (int layer = 0; layer < 2; layer++) {
        const float* s_w = (layer == 0) ? s_w1 : s_w2;
        #pragma unroll
        for (int q = 0; q < 16; q++) {
            ulonglong2 vA = ((const ulonglong2*)arowA)[q];
            ulonglong2 vB = ((const ulonglong2*)arowB)[q];
            finA[2*q] = vA.x; finA[2*q+1] = vA.y;
            finB[2*q] = vB.x; finB[2*q+1] = vB.y;
        }
        #pragma unroll 1
        for (int j = 0; j < 64; j += 4) {
            unsigned long long a0 = 0, a1 = 0, a2 = 0, a3 = 0;
            unsigned long long c0 = 0, c1 = 0, c2 = 0, c3 = 0;
            const ulonglong2* r0 = (const ulonglong2*)(s_w + (j + 0) * 64);
            const ulonglong2* r1 = (const ulonglong2*)(s_w + (j + 1) * 64);
            const ulonglong2* r2 = (const ulonglong2*)(s_w + (j + 2) * 64);
            const ulonglong2* r3 = (const ulonglong2*)(s_w + (j + 3) * 64);
            #pragma unroll
            for (int q = 0; q < 16; q++) {
                unsigned long long pA0 = finA[2*q], pA1 = finA[2*q+1];
                unsigned long long pB0 = finB[2*q], pB1 = finB[2*q+1];
                ulonglong2 wa = r0[q];
                fma2(a0, pA0, wa.x); fma2(a0, pA1, wa.y);
                fma2(c0, pB0, wa.x); fma2(c0, pB1, wa.y);
                ulonglong2 wb = r1[q];
                fma2(a1, pA0, wb.x); fma2(a1, pA1, wb.y);
                fma2(c1, pB0, wb.x); fma2(c1, pB1, wb.y);
                ulonglong2 wc = r2[q];
                fma2(a2, pA0, wc.x); fma2(a2, pA1, wc.y);
                fma2(c2, pB0, wc.x); fma2(c2, pB1, wc.y);
                ulonglong2 wd = r3[q];
                fma2(a3, pA0, wd.x); fma2(a3, pA1, wd.y);
                fma2(c3, pB0, wd.x); fma2(c3, pB1, wd.y);
            }
            float2 s0 = upk(a0), s1 = upk(a1), s2 = upk(a2), s3 = upk(a3);
            float2 t0 = upk(c0), t1 = upk(c1), t2 = upk(c2), t3 = upk(c3);
            ((float4*)arowA)[j >> 2] = make_float4(fmaxf(s0.x + s0.y, 0.f),
                                                   fmaxf(s1.x + s1.y, 0.f),
                                                   fmaxf(s2.x + s2.y, 0.f),
                                                   fmaxf(s3.x + s3.y, 0.f));
            ((float4*)arowB)[j >> 2] = make_float4(fmaxf(t0.x + t0.y, 0.f),
                                                   fmaxf(t1.x + t1.y, 0.f),
                                                   fmaxf(t2.x + t2.y, 0.f),
                                                   fmaxf(t3.x + t3.y, 0.f));
        }
    }

    // ---- output layer: 64 -> 3, + bias ----
    #pragma unroll
    for (int q = 0; q < 16; q++) {
        ulonglong2 vA = ((const ulonglong2*)arowA)[q];
        ulonglong2 vB = ((const ulonglong2*)arowB)[q];
        finA[2*q] = vA.x; finA[2*q+1] = vA.y;
        finB[2*q] = vB.x; finB[2*q+1] = vB.y;
    }
    {
        unsigned long long a0 = 0, a1 = 0, a2 = 0;
        unsigned long long c0 = 0, c1 = 0, c2 = 0;
        const ulonglong2* r0 = (const ulonglong2*)(s_wo + 0);
        const ulonglong2* r1 = (const ulonglong2*)(s_wo + 64);
        const ulonglong2* r2 = (const ulonglong2*)(s_wo + 128);
        #pragma unroll
        for (int q = 0; q < 16; q++) {
            unsigned long long pA0 = finA[2*q], pA1 = finA[2*q+1];
            unsigned long long pB0 = finB[2*q], pB1 = finB[2*q+1];
            ulonglong2 wa = r0[q];
            fma2(a0, pA0, wa.x); fma2(a0, pA1, wa.y);
            fma2(c0, pB0, wa.x); fma2(c0, pB1, wa.y);
            ulonglong2 wb = r1[q];
            fma2(a1, pA0, wb.x); fma2(a1, pA1, wb.y);
            fma2(c1, pB0, wb.x); fma2(c1, pB1, wb.y);
            ulonglong2 wc = r2[q];
            fma2(a2, pA0, wc.x); fma2(a2, pA1, wc.y);
            fma2(c2, pB0, wc.x); fma2(c2, pB1, wc.y);
        }
        float2 s0 = upk(a0), s1 = upk(a1), s2 = upk(a2);
        float2 t0 = upk(c0), t1 = upk(c1), t2 = upk(c2);
        const float bo0 = s_bo[0], bo1 = s_bo[1], bo2 = s_bo[2];
        const int nA = __ldg(&g_perm[iA]);
        size_t obA = (size_t)nA * 3;
        out[obA + 0] = bo0 + s0.x + s0.y;
        out[obA + 1] = bo1 + s1.x + s1.y;
        out[obA + 2] = bo2 + s2.x + s2.y;
        if (hasB) {
            const int nB = __ldg(&g_perm[iB]);
            size_t obB = (size_t)nB * 3;
            out[obB + 0] = bo0 + t0.x + t0.y;
            out[obB + 1] = bo1 + t1.x + t1.y;
            out[obB + 2] = bo2 + t2.x + t2.y;
        }
    }
}

extern "C" void kernel_launch(void* const* d_in, const int* in_sizes, int n_in,
                              void* d_out, int out_size)
{
    const float4* x     = (const float4*)d_in[0];
    const float2* table = (const float2*)d_in[1];
    const float*  w0    = (const float*)d_in[2];
    const float*  w1    = (const float*)d_in[3];
    const float*  w2    = (const float*)d_in[4];
    const float*  w_out = (const float*)d_in[5];
    const float*  b_out = (const float*)d_in[6];
    float* out = (float*)d_out;
    const int N = in_sizes[0] / 4;

    // Replicate numpy's RES computation bit-exactly (same aarch64 glibc pow/floor).
    Res4 res;
    const double minr[4] = {16.0, 16.0, 16.0, 16.0};
    const double maxr[4] = {256.0, 256.0, 256.0, 128.0};
    for (int d = 0; d < 4; d++) {
        double g = pow(maxr[d] / minr[d], 1.0 / 15.0);
        for (int l = 0; l < NLEV; l++) {
            res.v[l][d] = (int)floor(minr[d] * pow(g, (double)l));
        }
    }

    size_t smem = (size_t)(WTOT + 2 * MBLK * ACT_STRIDE) * sizeof(float);
    cudaFuncSetAttribute(ingp_mlp, cudaFuncAttributeMaxDynamicSharedMemorySize, (int)smem);

    const int pgrid = (N + SBLK - 1) / SBLK;

    // spatial counting sort: hist -> scan -> scatter (perm)
    sort_zero<<<(NBINS + SBLK - 1) / SBLK, SBLK>>>();
    sort_hist<<<pgrid, SBLK>>>(x, N);
    sort_scan<<<1, 1024>>>();
    sort_scatter<<<pgrid, SBLK>>>(x, N);

    int egrid = (N + EBLK - 1) / EBLK;
    ingp_encode<<<egrid, EBLK>>>(x, table, N, res);
    int mgrid = (N + 2 * MBLK - 1) / (2 * MBLK);
    ingp_mlp<<<mgrid, MBLK, smem>>>(w0, w1, w2, w_out, b_out, out, N);
}